// round 2
// baseline (speedup 1.0000x reference)
#include <cuda_runtime.h>

// Problem constants
#define BATCH_H   64      // B*H = 4*16
#define S_LEN     1024
#define DHEAD     64
#define BQ        64
#define BK        64
#define KPITCH    68      // padded pitch for K/P tiles (272B rows -> conflict-free)
#define NTHREADS  256

#define N_ELEM    (1u << 26)   // 4*16*1024*1024 mask elements
#define MASK_WORDS (1u << 21)  // N_ELEM / 32

// 8 MB packed dropout-keep bitmask (bit i of word w = element w*32+i)
__device__ unsigned g_mask[MASK_WORDS];

__device__ __forceinline__ unsigned rotl32(unsigned x, int r) {
    return __funnelshift_l(x, x, r);
}

// ---------------------------------------------------------------------------
// Kernel A: reproduce jax.random.bernoulli(key(42), 0.5, (4,16,1024,1024))
// under jax_threefry_partitionable=True (JAX >= 0.5 default):
//   per element i:  (hi, lo) = (0, i)
//   (o0, o1) = threefry2x32(key=(0,42), x=(hi, lo))
//   bits = o0 ^ o1 ;  keep = bits < 2^31  (uniform<0.5 <=> bit31==0)
// ---------------------------------------------------------------------------
__global__ void __launch_bounds__(256) maskgen_kernel() {
    unsigned i = blockIdx.x * 256u + threadIdx.x;   // 0 .. 2^26-1

    const unsigned ks0 = 0u;
    const unsigned ks1 = 42u;
    const unsigned ks2 = 0u ^ 42u ^ 0x1BD11BDAu;

    unsigned x0 = 0u + ks0;      // hi word of counter = 0
    unsigned x1 = i  + ks1;      // lo word of counter = i

#define TF_R(r) { x0 += x1; x1 = rotl32(x1, (r)); x1 ^= x0; }
    TF_R(13) TF_R(15) TF_R(26) TF_R(6)
    x0 += ks1; x1 += ks2 + 1u;
    TF_R(17) TF_R(29) TF_R(16) TF_R(24)
    x0 += ks2; x1 += ks0 + 2u;
    TF_R(13) TF_R(15) TF_R(26) TF_R(6)
    x0 += ks0; x1 += ks1 + 3u;
    TF_R(17) TF_R(29) TF_R(16) TF_R(24)
    x0 += ks1; x1 += ks2 + 4u;
    TF_R(13) TF_R(15) TF_R(26) TF_R(6)
    x0 += ks2; x1 += ks0 + 5u;
#undef TF_R

    unsigned bits = x0 ^ x1;
    unsigned b = __ballot_sync(0xffffffffu, (bits & 0x80000000u) == 0u);
    if ((threadIdx.x & 31u) == 0u) {
        g_mask[i >> 5] = b;
    }
}

// ---------------------------------------------------------------------------
// Kernel B: fp32 flash attention with pre-softmax dropout (masked -> 0, kept -> 2x)
// Grid: (S/BQ = 16, B*H = 64). CTA: 256 threads (16x16), per-thread 4x4 tile.
//   S-tile columns per thread: kk = tx + 16*j  (stride-16; conflict-free K reads)
//   O-tile columns per thread: dv = tx*4 + j   (contiguous; conflict-free V reads)
// ---------------------------------------------------------------------------
__global__ void __launch_bounds__(NTHREADS) attn_kernel(
    const float* __restrict__ Q,
    const float* __restrict__ K,
    const float* __restrict__ V,
    float* __restrict__ Out)
{
    extern __shared__ float smem[];
    float* Qs = smem;                      // [64][64]   16 KB
    float* Ks = smem + BQ * DHEAD;         // [64][68]   17 KB
    float* Vs = Ks + BK * KPITCH;          // [64][64]   16 KB
    float* Ps = Ks;                        // P^T aliases K tile (K dead after S)

    const int bh  = blockIdx.y;
    const int q0  = blockIdx.x * BQ;
    const int tid = threadIdx.x;
    const int tx  = tid & 15;
    const int ty  = tid >> 4;

    const float* Qb = Q + ((size_t)bh * S_LEN + q0) * DHEAD;
    const float* Kb = K + (size_t)bh * S_LEN * DHEAD;
    const float* Vb = V + (size_t)bh * S_LEN * DHEAD;

    // Load Q tile (64x64): 256 threads x 4 float4, coalesced
    #pragma unroll
    for (int r = 0; r < 4; r++) {
        int idx = tid + r * NTHREADS;
        int row = idx >> 4;
        int ch  = idx & 15;
        *(float4*)(Qs + row * DHEAD + ch * 4) =
            *(const float4*)(Qb + row * DHEAD + ch * 4);
    }

    float m[4], l[4], o[4][4];
    #pragma unroll
    for (int i = 0; i < 4; i++) {
        m[i] = -1e30f; l[i] = 0.0f;
        #pragma unroll
        for (int j = 0; j < 4; j++) o[i][j] = 0.0f;
    }

    for (int kt = 0; kt < 16; kt++) {
        __syncthreads();   // previous PV reads of Ps/Vs complete
        const float* Ktile = Kb + kt * BK * DHEAD;
        const float* Vtile = Vb + kt * BK * DHEAD;
        #pragma unroll
        for (int r = 0; r < 4; r++) {
            int idx = tid + r * NTHREADS;
            int row = idx >> 4;
            int ch  = idx & 15;
            *(float4*)(Ks + row * KPITCH + ch * 4) =
                *(const float4*)(Ktile + row * DHEAD + ch * 4);
            *(float4*)(Vs + row * DHEAD + ch * 4) =
                *(const float4*)(Vtile + row * DHEAD + ch * 4);
        }
        __syncthreads();

        // ---- S = Q @ K^T (per-thread 4x4), dot-product over d in float4 chunks
        float s[4][4] = {};
        #pragma unroll
        for (int d4 = 0; d4 < 16; d4++) {
            float4 qv[4], kv[4];
            #pragma unroll
            for (int i = 0; i < 4; i++)
                qv[i] = *(const float4*)(Qs + (ty * 4 + i) * DHEAD + d4 * 4);
            #pragma unroll
            for (int j = 0; j < 4; j++)
                kv[j] = *(const float4*)(Ks + (tx + 16 * j) * KPITCH + d4 * 4);
            #pragma unroll
            for (int i = 0; i < 4; i++)
                #pragma unroll
                for (int j = 0; j < 4; j++)
                    s[i][j] += qv[i].x * kv[j].x + qv[i].y * kv[j].y +
                               qv[i].z * kv[j].z + qv[i].w * kv[j].w;
        }

        // ---- dropout mask (0 or 2x) + online softmax (rows = 4 q's per thread)
        #pragma unroll
        for (int i = 0; i < 4; i++) {
            int widx = (bh << 15) + ((q0 + ty * 4 + i) << 5) + kt * 2;
            unsigned w0 = __ldg((const unsigned*)&g_mask[widx]);
            unsigned w1 = __ldg((const unsigned*)&g_mask[widx + 1]);
            #pragma unroll
            for (int j = 0; j < 4; j++) {
                unsigned w = (j < 2) ? w0 : w1;
                int bit = tx + ((j & 1) << 4);       // (tx + 16j) & 31
                s[i][j] = ((w >> bit) & 1u) ? (s[i][j] * 2.0f) : 0.0f;
            }
            float mt = fmaxf(fmaxf(s[i][0], s[i][1]), fmaxf(s[i][2], s[i][3]));
            #pragma unroll
            for (int off = 1; off < 16; off <<= 1)
                mt = fmaxf(mt, __shfl_xor_sync(0xffffffffu, mt, off));
            float mnew = fmaxf(m[i], mt);
            float corr = __expf(m[i] - mnew);
            float psum = 0.0f;
            #pragma unroll
            for (int j = 0; j < 4; j++) {
                s[i][j] = __expf(s[i][j] - mnew);
                psum += s[i][j];
            }
            #pragma unroll
            for (int off = 1; off < 16; off <<= 1)
                psum += __shfl_xor_sync(0xffffffffu, psum, off);
            l[i] = l[i] * corr + psum;
            m[i] = mnew;
            #pragma unroll
            for (int j = 0; j < 4; j++) o[i][j] *= corr;
        }

        __syncthreads();   // all Ks reads done before overwriting with P^T

        // ---- write P^T: Ps[k][q]; thread holds P[q=ty*4+i][k=tx+16j]
        #pragma unroll
        for (int j = 0; j < 4; j++) {
            float4 pv = make_float4(s[0][j], s[1][j], s[2][j], s[3][j]);
            *(float4*)(Ps + (tx + 16 * j) * KPITCH + ty * 4) = pv;
        }
        __syncthreads();

        // ---- O += P @ V : outer product over k; O cols dv = tx*4+j
        #pragma unroll 8
        for (int k = 0; k < BK; k++) {
            float4 pv = *(const float4*)(Ps + k * KPITCH + ty * 4);
            float4 vv = *(const float4*)(Vs + k * DHEAD + tx * 4);
            o[0][0] += pv.x * vv.x; o[0][1] += pv.x * vv.y;
            o[0][2] += pv.x * vv.z; o[0][3] += pv.x * vv.w;
            o[1][0] += pv.y * vv.x; o[1][1] += pv.y * vv.y;
            o[1][2] += pv.y * vv.z; o[1][3] += pv.y * vv.w;
            o[2][0] += pv.z * vv.x; o[2][1] += pv.z * vv.y;
            o[2][2] += pv.z * vv.z; o[2][3] += pv.z * vv.w;
            o[3][0] += pv.w * vv.x; o[3][1] += pv.w * vv.y;
            o[3][2] += pv.w * vv.z; o[3][3] += pv.w * vv.w;
        }
    }

    // ---- epilogue: O / l, coalesced float4 stores
    #pragma unroll
    for (int i = 0; i < 4; i++) {
        float inv = 1.0f / l[i];
        float4 out4 = make_float4(o[i][0] * inv, o[i][1] * inv,
                                  o[i][2] * inv, o[i][3] * inv);
        *(float4*)(Out + ((size_t)bh * S_LEN + q0 + ty * 4 + i) * DHEAD + tx * 4) = out4;
    }
}

// ---------------------------------------------------------------------------
extern "C" void kernel_launch(void* const* d_in, const int* in_sizes, int n_in,
                              void* d_out, int out_size) {
    const float* Q = (const float*)d_in[0];
    const float* K = (const float*)d_in[1];
    const float* V = (const float*)d_in[2];
    float* Out = (float*)d_out;

    // Phase 1: regenerate dropout mask (deterministic, same every launch)
    maskgen_kernel<<<N_ELEM / 256, 256>>>();

    // Phase 2: fused masked-softmax attention
    const int smem_bytes = (BQ * DHEAD + BK * KPITCH + BK * DHEAD) * (int)sizeof(float);
    cudaFuncSetAttribute(attn_kernel, cudaFuncAttributeMaxDynamicSharedMemorySize,
                         smem_bytes);
    dim3 grid(S_LEN / BQ, BATCH_H);
    attn_kernel<<<grid, NTHREADS, smem_bytes>>>(Q, K, V, Out);
}

// round 3
// speedup vs baseline: 1.1491x; 1.1491x over previous
#include <cuda_runtime.h>

// Problem constants
#define BATCH_H   64      // B*H = 4*16
#define S_LEN     1024
#define DHEAD     64
#define BQ        64
#define BK        64
#define KPITCH    68      // padded pitch for K/P tiles (272B rows -> conflict-free)
#define NTHREADS  256

// ---------------------------------------------------------------------------
// f32x2 packed math (Blackwell FFMA2 — only reachable via PTX)
// ---------------------------------------------------------------------------
__device__ __forceinline__ unsigned long long ffma2(
    unsigned long long a, unsigned long long b, unsigned long long c) {
    unsigned long long d;
    asm("fma.rn.f32x2 %0, %1, %2, %3;" : "=l"(d) : "l"(a), "l"(b), "l"(c));
    return d;
}
__device__ __forceinline__ unsigned long long fmul2(
    unsigned long long a, unsigned long long b) {
    unsigned long long d;
    asm("mul.rn.f32x2 %0, %1, %2;" : "=l"(d) : "l"(a), "l"(b));
    return d;
}
__device__ __forceinline__ unsigned long long bcast2(float x) {
    unsigned long long d;
    asm("mov.b64 %0, {%1, %1};" : "=l"(d) : "f"(x));
    return d;
}
__device__ __forceinline__ float2 unpack2(unsigned long long v) {
    float lo, hi;
    asm("mov.b64 {%0, %1}, %2;" : "=f"(lo), "=f"(hi) : "l"(v));
    return make_float2(lo, hi);
}

__device__ __forceinline__ unsigned rotl32(unsigned x, int r) {
    return __funnelshift_l(x, x, r);
}

// ---------------------------------------------------------------------------
// Threefry2x32(key=(0,42), x=(0, i)), partitionable path:
// keep <=> bit31 of (out0 ^ out1) == 0
// ---------------------------------------------------------------------------
__device__ __forceinline__ unsigned tf_keep(unsigned i) {
    const unsigned ks0 = 0u;
    const unsigned ks1 = 42u;
    const unsigned ks2 = 0u ^ 42u ^ 0x1BD11BDAu;
    unsigned x0 = 0u + ks0;
    unsigned x1 = i + ks1;
#define TF_R(r) { x0 += x1; x1 = rotl32(x1, (r)); x1 ^= x0; }
    TF_R(13) TF_R(15) TF_R(26) TF_R(6)
    x0 += ks1; x1 += ks2 + 1u;
    TF_R(17) TF_R(29) TF_R(16) TF_R(24)
    x0 += ks2; x1 += ks0 + 2u;
    TF_R(13) TF_R(15) TF_R(26) TF_R(6)
    x0 += ks0; x1 += ks1 + 3u;
    TF_R(17) TF_R(29) TF_R(16) TF_R(24)
    x0 += ks1; x1 += ks2 + 4u;
    TF_R(13) TF_R(15) TF_R(26) TF_R(6)
    x0 += ks2; x1 += ks0 + 5u;
#undef TF_R
    return (((x0 ^ x1) >> 31) ^ 1u);   // 1 = keep
}

// ---------------------------------------------------------------------------
// Fused flash attention + inline threefry dropout (masked -> 0, kept -> 2x).
// Grid: (16, 64). CTA: 256 threads (16x16), per-thread 4 rows x 4 cols.
//   S cols per thread: kk = tx + 16*j ; O cols: dv = tx*4 + j
// GEMMs use fma.rn.f32x2: S pairs over d (natural pairs), PV pairs over dv.
// ---------------------------------------------------------------------------
__global__ void __launch_bounds__(NTHREADS) attn_kernel(
    const float* __restrict__ Q,
    const float* __restrict__ K,
    const float* __restrict__ V,
    float* __restrict__ Out)
{
    extern __shared__ float smem[];
    float* Qs = smem;                      // [64][64]
    float* Ks = smem + BQ * DHEAD;         // [64][68]
    float* Vs = Ks + BK * KPITCH;          // [64][64]
    float* Ps = Ks;                        // P^T aliases K tile

    const int bh  = blockIdx.y;
    const int q0  = blockIdx.x * BQ;
    const int tid = threadIdx.x;
    const int tx  = tid & 15;
    const int ty  = tid >> 4;

    const float* Qb = Q + ((size_t)bh * S_LEN + q0) * DHEAD;
    const float* Kb = K + (size_t)bh * S_LEN * DHEAD;
    const float* Vb = V + (size_t)bh * S_LEN * DHEAD;

    // Load Q tile (64x64)
    #pragma unroll
    for (int r = 0; r < 4; r++) {
        int idx = tid + r * NTHREADS;
        int row = idx >> 4;
        int ch  = idx & 15;
        *(float4*)(Qs + row * DHEAD + ch * 4) =
            *(const float4*)(Qb + row * DHEAD + ch * 4);
    }

    float m[4], l[4];
    unsigned long long o2[4][2];   // packed f32x2 output accumulators
    #pragma unroll
    for (int i = 0; i < 4; i++) {
        m[i] = -1e30f; l[i] = 0.0f;
        o2[i][0] = 0ULL; o2[i][1] = 0ULL;
    }

    // per-row base index into the (b,h,q,k) element space for threefry
    // elem idx = ((bh*1024 + q) * 1024) + k
    unsigned rowbase[4];
    #pragma unroll
    for (int i = 0; i < 4; i++)
        rowbase[i] = (((unsigned)bh * S_LEN + (unsigned)(q0 + ty * 4 + i)) << 10) + tx;

    for (int kt = 0; kt < 16; kt++) {
        __syncthreads();
        const float* Ktile = Kb + kt * BK * DHEAD;
        const float* Vtile = Vb + kt * BK * DHEAD;
        #pragma unroll
        for (int r = 0; r < 4; r++) {
            int idx = tid + r * NTHREADS;
            int row = idx >> 4;
            int ch  = idx & 15;
            *(float4*)(Ks + row * KPITCH + ch * 4) =
                *(const float4*)(Ktile + row * DHEAD + ch * 4);
            *(float4*)(Vs + row * DHEAD + ch * 4) =
                *(const float4*)(Vtile + row * DHEAD + ch * 4);
        }
        __syncthreads();

        // ---- S = Q @ K^T, f32x2 pairs over d. acc lanes = even/odd d partials
        unsigned long long acc2[4][4];
        #pragma unroll
        for (int i = 0; i < 4; i++)
            #pragma unroll
            for (int j = 0; j < 4; j++) acc2[i][j] = 0ULL;

        #pragma unroll
        for (int d4 = 0; d4 < 16; d4++) {
            ulonglong2 q2[4], k2[4];
            #pragma unroll
            for (int i = 0; i < 4; i++)
                q2[i] = *(const ulonglong2*)(Qs + (ty * 4 + i) * DHEAD + d4 * 4);
            #pragma unroll
            for (int j = 0; j < 4; j++)
                k2[j] = *(const ulonglong2*)(Ks + (tx + 16 * j) * KPITCH + d4 * 4);
            #pragma unroll
            for (int i = 0; i < 4; i++)
                #pragma unroll
                for (int j = 0; j < 4; j++) {
                    acc2[i][j] = ffma2(q2[i].x, k2[j].x, acc2[i][j]);
                    acc2[i][j] = ffma2(q2[i].y, k2[j].y, acc2[i][j]);
                }
        }

        // ---- inline dropout (threefry) + online softmax
        float s[4][4];
        #pragma unroll
        for (int i = 0; i < 4; i++) {
            unsigned base = rowbase[i] + (unsigned)(kt * 64);
            #pragma unroll
            for (int j = 0; j < 4; j++) {
                float2 p = unpack2(acc2[i][j]);
                float sv = p.x + p.y;
                unsigned keep = tf_keep(base + 16u * j);
                s[i][j] = keep ? (sv * 2.0f) : 0.0f;
            }
            float mt = fmaxf(fmaxf(s[i][0], s[i][1]), fmaxf(s[i][2], s[i][3]));
            #pragma unroll
            for (int off = 1; off < 16; off <<= 1)
                mt = fmaxf(mt, __shfl_xor_sync(0xffffffffu, mt, off));
            float mnew = fmaxf(m[i], mt);
            float corr = __expf(m[i] - mnew);
            float psum = 0.0f;
            #pragma unroll
            for (int j = 0; j < 4; j++) {
                s[i][j] = __expf(s[i][j] - mnew);
                psum += s[i][j];
            }
            #pragma unroll
            for (int off = 1; off < 16; off <<= 1)
                psum += __shfl_xor_sync(0xffffffffu, psum, off);
            l[i] = l[i] * corr + psum;
            m[i] = mnew;
            unsigned long long cd = bcast2(corr);
            o2[i][0] = fmul2(o2[i][0], cd);
            o2[i][1] = fmul2(o2[i][1], cd);
        }

        __syncthreads();   // Ks reads done before overwriting with P^T

        // ---- write P^T: Ps[k][q]
        #pragma unroll
        for (int j = 0; j < 4; j++) {
            float4 pv = make_float4(s[0][j], s[1][j], s[2][j], s[3][j]);
            *(float4*)(Ps + (tx + 16 * j) * KPITCH + ty * 4) = pv;
        }
        __syncthreads();

        // ---- O += P @ V, f32x2 pairs over dv columns
        #pragma unroll 8
        for (int k = 0; k < BK; k++) {
            float4 pv = *(const float4*)(Ps + k * KPITCH + ty * 4);
            ulonglong2 vv = *(const ulonglong2*)(Vs + k * DHEAD + tx * 4);
            unsigned long long pd;
            pd = bcast2(pv.x);
            o2[0][0] = ffma2(pd, vv.x, o2[0][0]);
            o2[0][1] = ffma2(pd, vv.y, o2[0][1]);
            pd = bcast2(pv.y);
            o2[1][0] = ffma2(pd, vv.x, o2[1][0]);
            o2[1][1] = ffma2(pd, vv.y, o2[1][1]);
            pd = bcast2(pv.z);
            o2[2][0] = ffma2(pd, vv.x, o2[2][0]);
            o2[2][1] = ffma2(pd, vv.y, o2[2][1]);
            pd = bcast2(pv.w);
            o2[3][0] = ffma2(pd, vv.x, o2[3][0]);
            o2[3][1] = ffma2(pd, vv.y, o2[3][1]);
        }
    }

    // ---- epilogue: O / l, coalesced float4 stores
    #pragma unroll
    for (int i = 0; i < 4; i++) {
        float inv = 1.0f / l[i];
        float2 a = unpack2(o2[i][0]);
        float2 b = unpack2(o2[i][1]);
        float4 out4 = make_float4(a.x * inv, a.y * inv, b.x * inv, b.y * inv);
        *(float4*)(Out + ((size_t)bh * S_LEN + q0 + ty * 4 + i) * DHEAD + tx * 4) = out4;
    }
}

// ---------------------------------------------------------------------------
extern "C" void kernel_launch(void* const* d_in, const int* in_sizes, int n_in,
                              void* d_out, int out_size) {
    const float* Q = (const float*)d_in[0];
    const float* K = (const float*)d_in[1];
    const float* V = (const float*)d_in[2];
    float* Out = (float*)d_out;

    const int smem_bytes = (BQ * DHEAD + BK * KPITCH + BK * DHEAD) * (int)sizeof(float);
    cudaFuncSetAttribute(attn_kernel, cudaFuncAttributeMaxDynamicSharedMemorySize,
                         smem_bytes);
    dim3 grid(S_LEN / BQ, BATCH_H);
    attn_kernel<<<grid, NTHREADS, smem_bytes>>>(Q, K, V, Out);
}

// round 4
// speedup vs baseline: 1.2005x; 1.0447x over previous
#include <cuda_runtime.h>

// Problem constants
#define BATCH_H   64      // B*H = 4*16
#define S_LEN     1024
#define DHEAD     64
#define BQ        64
#define BK        64
#define KPITCH    68      // padded pitch for K/P tiles (272B rows -> conflict-free)
#define NTHREADS  256

// ---------------------------------------------------------------------------
// f32x2 packed math (Blackwell FFMA2 — only reachable via PTX)
// ---------------------------------------------------------------------------
__device__ __forceinline__ unsigned long long ffma2(
    unsigned long long a, unsigned long long b, unsigned long long c) {
    unsigned long long d;
    asm("fma.rn.f32x2 %0, %1, %2, %3;" : "=l"(d) : "l"(a), "l"(b), "l"(c));
    return d;
}
__device__ __forceinline__ unsigned long long fmul2(
    unsigned long long a, unsigned long long b) {
    unsigned long long d;
    asm("mul.rn.f32x2 %0, %1, %2;" : "=l"(d) : "l"(a), "l"(b));
    return d;
}
__device__ __forceinline__ unsigned long long bcast2(float x) {
    unsigned long long d;
    asm("mov.b64 %0, {%1, %1};" : "=l"(d) : "f"(x));
    return d;
}
__device__ __forceinline__ float2 unpack2(unsigned long long v) {
    float lo, hi;
    asm("mov.b64 {%0, %1}, %2;" : "=f"(lo), "=f"(hi) : "l"(v));
    return make_float2(lo, hi);
}

__device__ __forceinline__ unsigned rotl32(unsigned x, int r) {
    return __funnelshift_l(x, x, r);
}

// ---------------------------------------------------------------------------
// Two interleaved Threefry2x32(key=(0,42), x=(0,i)) evaluations (2-way ILP).
// Returns keep(ia) in bit0, keep(ib) in bit1.  keep <=> bit31(out0^out1)==0.
// ---------------------------------------------------------------------------
__device__ __forceinline__ unsigned tf_keep2(unsigned ia, unsigned ib) {
    const unsigned ks1 = 42u;
    const unsigned ks2 = 42u ^ 0x1BD11BDAu;
    unsigned a0 = 0u, a1 = ia + ks1;
    unsigned b0 = 0u, b1 = ib + ks1;
#define R2(r) { a0 += a1; b0 += b1; a1 = rotl32(a1,(r)); b1 = rotl32(b1,(r)); \
                a1 ^= a0; b1 ^= b0; }
    R2(13) R2(15) R2(26) R2(6)
    a0 += ks1; a1 += ks2 + 1u;  b0 += ks1; b1 += ks2 + 1u;
    R2(17) R2(29) R2(16) R2(24)
    a0 += ks2; a1 += 2u;        b0 += ks2; b1 += 2u;
    R2(13) R2(15) R2(26) R2(6)
    a1 += ks1 + 3u;             b1 += ks1 + 3u;        // ks0 = 0
    R2(17) R2(29) R2(16) R2(24)
    a0 += ks1; a1 += ks2 + 4u;  b0 += ks1; b1 += ks2 + 4u;
    R2(13) R2(15) R2(26) R2(6)
    a0 += ks2; a1 += 5u;        b0 += ks2; b1 += 5u;
#undef R2
    unsigned ka = ((a0 ^ a1) >> 31) ^ 1u;
    unsigned kb = ((b0 ^ b1) >> 31) ^ 1u;
    return ka | (kb << 1);
}

// ---------------------------------------------------------------------------
// Fused flash attention; threefry for tile kt+1 interleaved into the GEMM
// sections of tile kt so the alu pipe (threefry) and fma pipe (FFMA2) overlap.
// Grid: (16, 64). CTA: 256 threads (16x16), per-thread 4 rows x 4 cols.
//   S cols per thread: kk = tx + 16*j ; O cols: dv = tx*4 + j
// ---------------------------------------------------------------------------
__global__ void __launch_bounds__(NTHREADS) attn_kernel(
    const float* __restrict__ Q,
    const float* __restrict__ K,
    const float* __restrict__ V,
    float* __restrict__ Out)
{
    extern __shared__ float smem[];
    float* Qs = smem;                      // [64][64]
    float* Ks = smem + BQ * DHEAD;         // [64][68]
    float* Vs = Ks + BK * KPITCH;          // [64][64]
    float* Ps = Ks;                        // P^T aliases K tile

    const int bh  = blockIdx.y;
    const int q0  = blockIdx.x * BQ;
    const int tid = threadIdx.x;
    const int tx  = tid & 15;
    const int ty  = tid >> 4;

    const float* Qb = Q + ((size_t)bh * S_LEN + q0) * DHEAD;
    const float* Kb = K + (size_t)bh * S_LEN * DHEAD;
    const float* Vb = V + (size_t)bh * S_LEN * DHEAD;

    // Load Q tile (64x64)
    #pragma unroll
    for (int r = 0; r < 4; r++) {
        int idx = tid + r * NTHREADS;
        int row = idx >> 4;
        int ch  = idx & 15;
        *(float4*)(Qs + row * DHEAD + ch * 4) =
            *(const float4*)(Qb + row * DHEAD + ch * 4);
    }

    float m[4], l[4];
    unsigned long long o2[4][2];
    #pragma unroll
    for (int i = 0; i < 4; i++) {
        m[i] = -1e30f; l[i] = 0.0f;
        o2[i][0] = 0ULL; o2[i][1] = 0ULL;
    }

    // element index for (row i, col tx+16j) at tile t:
    //   rb0 + (i<<10) + t*64 + 16*j,  rb0 = ((bh*1024 + q0 + ty*4)<<10) + tx
    const unsigned rb0 =
        ((((unsigned)bh << 10) + (unsigned)(q0 + ty * 4)) << 10) + (unsigned)tx;

    // Prologue: all 16 keep bits for tile 0 (bit layout: i*4 + j)
    unsigned mask_cur = 0;
    #pragma unroll 1
    for (int g = 0; g < 4; g++) {
        unsigned e = rb0 + ((unsigned)g << 10);
        mask_cur |= tf_keep2(e, e + 16u) << (g * 4);
        mask_cur |= tf_keep2(e + 32u, e + 48u) << (g * 4 + 2);
    }

    for (int kt = 0; kt < 16; kt++) {
        __syncthreads();
        const float* Ktile = Kb + kt * BK * DHEAD;
        const float* Vtile = Vb + kt * BK * DHEAD;
        #pragma unroll
        for (int r = 0; r < 4; r++) {
            int idx = tid + r * NTHREADS;
            int row = idx >> 4;
            int ch  = idx & 15;
            *(float4*)(Ks + row * KPITCH + ch * 4) =
                *(const float4*)(Ktile + row * DHEAD + ch * 4);
            *(float4*)(Vs + row * DHEAD + ch * 4) =
                *(const float4*)(Vtile + row * DHEAD + ch * 4);
        }
        __syncthreads();

        unsigned mask_next = 0;
        const unsigned nb = rb0 + (unsigned)((kt + 1) * 64);

        // ---- S = Q @ K^T (FFMA2 pairs over d) + 8 threefry bits for kt+1
        unsigned long long acc2[4][4];
        #pragma unroll
        for (int i = 0; i < 4; i++)
            #pragma unroll
            for (int j = 0; j < 4; j++) acc2[i][j] = 0ULL;

        #pragma unroll 1
        for (int g = 0; g < 4; g++) {
            #pragma unroll
            for (int d4i = 0; d4i < 4; d4i++) {
                int d4 = g * 4 + d4i;
                ulonglong2 q2[4], k2[4];
                #pragma unroll
                for (int i = 0; i < 4; i++)
                    q2[i] = *(const ulonglong2*)(Qs + (ty * 4 + i) * DHEAD + d4 * 4);
                #pragma unroll
                for (int j = 0; j < 4; j++)
                    k2[j] = *(const ulonglong2*)(Ks + (tx + 16 * j) * KPITCH + d4 * 4);
                #pragma unroll
                for (int i = 0; i < 4; i++)
                    #pragma unroll
                    for (int j = 0; j < 4; j++) {
                        acc2[i][j] = ffma2(q2[i].x, k2[j].x, acc2[i][j]);
                        acc2[i][j] = ffma2(q2[i].y, k2[j].y, acc2[i][j]);
                    }
            }
            unsigned e = nb + ((unsigned)g << 10);
            mask_next |= tf_keep2(e, e + 16u) << (g * 4);   // bits j=0,1 of row g
        }

        // ---- dropout (mask_cur) + online softmax
        float s[4][4];
        #pragma unroll
        for (int i = 0; i < 4; i++) {
            #pragma unroll
            for (int j = 0; j < 4; j++) {
                float2 p = unpack2(acc2[i][j]);
                float sv = p.x + p.y;
                s[i][j] = ((mask_cur >> (i * 4 + j)) & 1u) ? (sv * 2.0f) : 0.0f;
            }
            float mt = fmaxf(fmaxf(s[i][0], s[i][1]), fmaxf(s[i][2], s[i][3]));
            #pragma unroll
            for (int off = 1; off < 16; off <<= 1)
                mt = fmaxf(mt, __shfl_xor_sync(0xffffffffu, mt, off));
            float mnew = fmaxf(m[i], mt);
            float corr = __expf(m[i] - mnew);
            float psum = 0.0f;
            #pragma unroll
            for (int j = 0; j < 4; j++) {
                s[i][j] = __expf(s[i][j] - mnew);
                psum += s[i][j];
            }
            #pragma unroll
            for (int off = 1; off < 16; off <<= 1)
                psum += __shfl_xor_sync(0xffffffffu, psum, off);
            l[i] = l[i] * corr + psum;
            m[i] = mnew;
            unsigned long long cd = bcast2(corr);
            o2[i][0] = fmul2(o2[i][0], cd);
            o2[i][1] = fmul2(o2[i][1], cd);
        }

        __syncthreads();   // Ks reads done before overwriting with P^T

        // ---- write P^T: Ps[k][q]
        #pragma unroll
        for (int j = 0; j < 4; j++) {
            float4 pv = make_float4(s[0][j], s[1][j], s[2][j], s[3][j]);
            *(float4*)(Ps + (tx + 16 * j) * KPITCH + ty * 4) = pv;
        }
        __syncthreads();

        // ---- O += P @ V (FFMA2 pairs over dv) + remaining 8 bits for kt+1
        #pragma unroll 1
        for (int g = 0; g < 4; g++) {
            #pragma unroll
            for (int kk = 0; kk < 16; kk++) {
                int k = g * 16 + kk;
                float4 pv = *(const float4*)(Ps + k * KPITCH + ty * 4);
                ulonglong2 vv = *(const ulonglong2*)(Vs + k * DHEAD + tx * 4);
                unsigned long long pd;
                pd = bcast2(pv.x);
                o2[0][0] = ffma2(pd, vv.x, o2[0][0]);
                o2[0][1] = ffma2(pd, vv.y, o2[0][1]);
                pd = bcast2(pv.y);
                o2[1][0] = ffma2(pd, vv.x, o2[1][0]);
                o2[1][1] = ffma2(pd, vv.y, o2[1][1]);
                pd = bcast2(pv.z);
                o2[2][0] = ffma2(pd, vv.x, o2[2][0]);
                o2[2][1] = ffma2(pd, vv.y, o2[2][1]);
                pd = bcast2(pv.w);
                o2[3][0] = ffma2(pd, vv.x, o2[3][0]);
                o2[3][1] = ffma2(pd, vv.y, o2[3][1]);
            }
            unsigned e = nb + ((unsigned)g << 10) + 32u;
            mask_next |= tf_keep2(e, e + 16u) << (g * 4 + 2);  // bits j=2,3 of row g
        }

        mask_cur = mask_next;
    }

    // ---- epilogue: O / l, coalesced float4 stores
    #pragma unroll
    for (int i = 0; i < 4; i++) {
        float inv = 1.0f / l[i];
        float2 a = unpack2(o2[i][0]);
        float2 b = unpack2(o2[i][1]);
        float4 out4 = make_float4(a.x * inv, a.y * inv, b.x * inv, b.y * inv);
        *(float4*)(Out + ((size_t)bh * S_LEN + q0 + ty * 4 + i) * DHEAD + tx * 4) = out4;
    }
}

// ---------------------------------------------------------------------------
extern "C" void kernel_launch(void* const* d_in, const int* in_sizes, int n_in,
                              void* d_out, int out_size) {
    const float* Q = (const float*)d_in[0];
    const float* K = (const float*)d_in[1];
    const float* V = (const float*)d_in[2];
    float* Out = (float*)d_out;

    const int smem_bytes = (BQ * DHEAD + BK * KPITCH + BK * DHEAD) * (int)sizeof(float);
    cudaFuncSetAttribute(attn_kernel, cudaFuncAttributeMaxDynamicSharedMemorySize,
                         smem_bytes);
    dim3 grid(S_LEN / BQ, BATCH_H);
    attn_kernel<<<grid, NTHREADS, smem_bytes>>>(Q, K, V, Out);
}

// round 6
// speedup vs baseline: 1.4475x; 1.2058x over previous
#include <cuda_runtime.h>
#include <cstdint>

// Problem constants
#define BHN   64
#define SLEN  1024
#define DH    64
#define BQ    64            // q rows per CTA (16 per warp)
#define NT    128
#define NKT   16
#define PITCHB 144          // smem row pitch in bytes (72 bf16) -> conflict-free ldmatrix

#define EXP_SHIFT 40.0f

// smem byte offsets: 6 tiles of 64 rows x 144B = 9216B each
#define SM_QH 0
#define SM_QL 9216
#define SM_KH 18432
#define SM_KL 27648
#define SM_VH 36864
#define SM_VL 46080
#define SM_TOTAL 55296

// ---------------------------------------------------------------------------
// helpers
// ---------------------------------------------------------------------------
__device__ __forceinline__ uint32_t smem_u32(const void* p) {
    uint32_t a;
    asm("{ .reg .u64 t; cvta.to.shared.u64 t, %1; cvt.u32.u64 %0, t; }"
        : "=r"(a) : "l"(p));
    return a;
}
// pack two fp32 -> bf16x2 (lo arg in low 16 bits)
__device__ __forceinline__ uint32_t pack_bf16x2(float lo, float hi) {
    uint32_t r;
    asm("cvt.rn.bf16x2.f32 %0, %1, %2;" : "=r"(r) : "f"(hi), "f"(lo));
    return r;
}
__device__ __forceinline__ float bflo(uint32_t p) { return __uint_as_float(p << 16); }
__device__ __forceinline__ float bfhi(uint32_t p) { return __uint_as_float(p & 0xFFFF0000u); }

__device__ __forceinline__ void cvt_split4(float4 v, uint32_t& h0, uint32_t& h1,
                                           uint32_t& l0, uint32_t& l1) {
    h0 = pack_bf16x2(v.x, v.y);
    h1 = pack_bf16x2(v.z, v.w);
    l0 = pack_bf16x2(v.x - bflo(h0), v.y - bfhi(h0));
    l1 = pack_bf16x2(v.z - bflo(h1), v.w - bfhi(h1));
}

__device__ __forceinline__ void ldmx4(uint32_t addr, uint32_t r[4]) {
    asm volatile("ldmatrix.sync.aligned.m8n8.x4.shared.b16 {%0,%1,%2,%3}, [%4];"
                 : "=r"(r[0]), "=r"(r[1]), "=r"(r[2]), "=r"(r[3]) : "r"(addr));
}

__device__ __forceinline__ void mma_bf16(float c[4], uint32_t a0, uint32_t a1,
                                         uint32_t a2, uint32_t a3,
                                         uint32_t b0, uint32_t b1) {
    asm volatile(
        "mma.sync.aligned.m16n8k16.row.col.f32.bf16.bf16.f32 "
        "{%0,%1,%2,%3}, {%4,%5,%6,%7}, {%8,%9}, {%0,%1,%2,%3};"
        : "+f"(c[0]), "+f"(c[1]), "+f"(c[2]), "+f"(c[3])
        : "r"(a0), "r"(a1), "r"(a2), "r"(a3), "r"(b0), "r"(b1));
}

// ---------------------------------------------------------------------------
// Threefry2x32(key=(0,42), x=(0,i)) x2 interleaved; keep <=> bit31(o0^o1)==0
// (validated in R2/R4)
// ---------------------------------------------------------------------------
__device__ __forceinline__ unsigned rotl32(unsigned x, int r) {
    return __funnelshift_l(x, x, r);
}
__device__ __forceinline__ unsigned tf_keep2(unsigned ia, unsigned ib) {
    const unsigned ks1 = 42u;
    const unsigned ks2 = 42u ^ 0x1BD11BDAu;
    unsigned a0 = 0u, a1 = ia + ks1;
    unsigned b0 = 0u, b1 = ib + ks1;
#define R2(r) { a0 += a1; b0 += b1; a1 = rotl32(a1,(r)); b1 = rotl32(b1,(r)); \
                a1 ^= a0; b1 ^= b0; }
    R2(13) R2(15) R2(26) R2(6)
    a0 += ks1; a1 += ks2 + 1u;  b0 += ks1; b1 += ks2 + 1u;
    R2(17) R2(29) R2(16) R2(24)
    a0 += ks2; a1 += 2u;        b0 += ks2; b1 += 2u;
    R2(13) R2(15) R2(26) R2(6)
    a1 += ks1 + 3u;             b1 += ks1 + 3u;
    R2(17) R2(29) R2(16) R2(24)
    a0 += ks1; a1 += ks2 + 4u;  b0 += ks1; b1 += ks2 + 4u;
    R2(13) R2(15) R2(26) R2(6)
    a0 += ks2; a1 += 5u;        b0 += ks2; b1 += 5u;
#undef R2
    unsigned ka = ((a0 ^ a1) >> 31) ^ 1u;
    unsigned kb = ((b0 ^ b1) >> 31) ^ 1u;
    return ka | (kb << 1);
}

// ---------------------------------------------------------------------------
// bf16x3 HMMA flash attention with inline threefry dropout and fixed-shift
// softmax. P stays in registers (C-fragment == A-fragment layout).
// ---------------------------------------------------------------------------
__global__ void __launch_bounds__(NT) attn_mma_kernel(
    const float* __restrict__ Q,
    const float* __restrict__ K,
    const float* __restrict__ V,
    float* __restrict__ Out)
{
    extern __shared__ char sm[];
    const uint32_t smb = smem_u32(sm);
    const int tid  = threadIdx.x;
    const int lane = tid & 31;
    const int warp = tid >> 5;
    const int bh   = blockIdx.y;
    const int q0   = blockIdx.x * BQ;

    const float* Qb = Q + ((size_t)bh * SLEN + q0) * DH;
    const float* Kb = K + (size_t)bh * SLEN * DH;
    const float* Vb = V + (size_t)bh * SLEN * DH;

    // ---- Q tile -> smem bf16 hi/lo (rows=q, cols=d)
    #pragma unroll
    for (int i = 0; i < 8; i++) {
        int idx = tid + i * NT;              // 0..1023 float4s
        int row = idx >> 4, c4 = idx & 15;
        float4 v = *(const float4*)(Qb + row * DH + c4 * 4);
        uint32_t h0, h1, l0, l1;
        cvt_split4(v, h0, h1, l0, l1);
        *(uint2*)(sm + SM_QH + row * PITCHB + c4 * 8) = make_uint2(h0, h1);
        *(uint2*)(sm + SM_QL + row * PITCHB + c4 * 8) = make_uint2(l0, l1);
    }
    __syncthreads();

    // ldmatrix lane mappings
    const int arow = (lane & 7) + ((lane >> 3) & 1) * 8;  // A: m0 r0-7, m1 r8-15, m2 r0-7(+8col), m3 r8-15(+8col)
    const int ach  = (lane >> 4);
    const int brow = (lane & 7) + (lane >> 4) * 8;        // B: m0 n0-7 c0, m1 n0-7 c+8, m2 n8-15 c0, m3 n8-15 c+8
    const int bch  = (lane >> 3) & 1;

    // ---- per-warp persistent Q fragments (4 k-steps, hi+lo)
    uint32_t qh[4][4], ql[4][4];
    {
        uint32_t aoff = (uint32_t)((warp * 16 + arow) * PITCHB + ach * 16);
        #pragma unroll
        for (int ks = 0; ks < 4; ks++) {
            ldmx4(smb + SM_QH + aoff + ks * 32, qh[ks]);
            ldmx4(smb + SM_QL + aoff + ks * 32, ql[ks]);
        }
    }

    float o[8][4];
    #pragma unroll
    for (int nb = 0; nb < 8; nb++)
        o[nb][0] = o[nb][1] = o[nb][2] = o[nb][3] = 0.0f;
    float lsum0 = 0.0f, lsum1 = 0.0f;

    // threefry element base for row (q0+warp*16+lane/4), col offset 2*(lane&3)
    const unsigned er0 =
        (((unsigned)(bh * SLEN + q0 + warp * 16 + (lane >> 2))) << 10) + 2u * (lane & 3);

    const uint32_t boff0 = (uint32_t)(brow * PITCHB + bch * 16);

    for (int kt = 0; kt < NKT; kt++) {
        __syncthreads();   // prior tile's ldmatrix reads of K/V done

        // ---- K tile (rows=key, cols=d) -> bf16 hi/lo
        const float* Kt = Kb + (size_t)kt * 64 * DH;
        #pragma unroll
        for (int i = 0; i < 8; i++) {
            int idx = tid + i * NT;
            int row = idx >> 4, c4 = idx & 15;
            float4 v = *(const float4*)(Kt + row * DH + c4 * 4);
            uint32_t h0, h1, l0, l1;
            cvt_split4(v, h0, h1, l0, l1);
            *(uint2*)(sm + SM_KH + row * PITCHB + c4 * 8) = make_uint2(h0, h1);
            *(uint2*)(sm + SM_KL + row * PITCHB + c4 * 8) = make_uint2(l0, l1);
        }
        // ---- V^T tile (rows=d, cols=key) -> bf16 hi/lo
        {
            int dcol = tid & 63, khf = tid >> 6;
            const float* vp = Vb + ((size_t)kt * 64 + khf * 32) * DH + dcol;
            uint32_t vh[16], vl[16];
            #pragma unroll
            for (int jp = 0; jp < 16; jp++) {
                float a = vp[(2 * jp) * DH];
                float b = vp[(2 * jp + 1) * DH];
                uint32_t h = pack_bf16x2(a, b);
                vh[jp] = h;
                vl[jp] = pack_bf16x2(a - bflo(h), b - bfhi(h));
            }
            char* v0 = sm + SM_VH + dcol * PITCHB + khf * 64;
            char* v1 = sm + SM_VL + dcol * PITCHB + khf * 64;
            #pragma unroll
            for (int g = 0; g < 4; g++) {
                *(uint4*)(v0 + g * 16) =
                    make_uint4(vh[4*g], vh[4*g+1], vh[4*g+2], vh[4*g+3]);
                *(uint4*)(v1 + g * 16) =
                    make_uint4(vl[4*g], vl[4*g+1], vl[4*g+2], vl[4*g+3]);
            }
        }

        // ---- threefry: 32 keep bits (2 rows x 16 cols) — overlaps the loads
        unsigned mask = 0;
        {
            unsigned e0 = er0 + (unsigned)(kt * 64);
            #pragma unroll
            for (int nb = 0; nb < 8; nb++) {
                unsigned ka = tf_keep2(e0 + 8u * nb, e0 + 8u * nb + 1u);
                unsigned kb2 = tf_keep2(e0 + 8192u + 8u * nb, e0 + 8192u + 8u * nb + 1u);
                mask |= (ka | (kb2 << 2)) << (nb * 4);
            }
        }
        __syncthreads();

        // ---- S = Q K^T : bf16x3 (QhKh + QhKl + QlKh)
        float s[8][4];
        #pragma unroll
        for (int nb = 0; nb < 8; nb++)
            s[nb][0] = s[nb][1] = s[nb][2] = s[nb][3] = 0.0f;

        #pragma unroll
        for (int ks = 0; ks < 4; ks++) {
            uint32_t kfh[4][4], kfl[4][4];
            #pragma unroll
            for (int np = 0; np < 4; np++) {
                uint32_t off = boff0 + (uint32_t)(np * 16 * PITCHB + ks * 32);
                ldmx4(smb + SM_KH + off, kfh[np]);
                ldmx4(smb + SM_KL + off, kfl[np]);
            }
            #pragma unroll
            for (int np = 0; np < 4; np++)
                #pragma unroll
                for (int h = 0; h < 2; h++) {
                    int nb = 2 * np + h;
                    mma_bf16(s[nb], qh[ks][0], qh[ks][1], qh[ks][2], qh[ks][3],
                             kfh[np][2*h], kfh[np][2*h+1]);
                    mma_bf16(s[nb], qh[ks][0], qh[ks][1], qh[ks][2], qh[ks][3],
                             kfl[np][2*h], kfl[np][2*h+1]);
                    mma_bf16(s[nb], ql[ks][0], ql[ks][1], ql[ks][2], ql[ks][3],
                             kfh[np][2*h], kfh[np][2*h+1]);
                }
        }

        // ---- dropout + fixed-shift softmax + pack P to bf16 hi/lo A-fragments
        uint32_t ph01[8], ph23[8], pl01[8], pl23[8];
        #pragma unroll
        for (int nb = 0; nb < 8; nb++) {
            unsigned mb = mask >> (nb * 4);
            float p0 = (mb & 1u) ? __expf(fmaf(s[nb][0], 2.0f, -EXP_SHIFT)) : 0.0f;
            float p1 = (mb & 2u) ? __expf(fmaf(s[nb][1], 2.0f, -EXP_SHIFT)) : 0.0f;
            float p2 = (mb & 4u) ? __expf(fmaf(s[nb][2], 2.0f, -EXP_SHIFT)) : 0.0f;
            float p3 = (mb & 8u) ? __expf(fmaf(s[nb][3], 2.0f, -EXP_SHIFT)) : 0.0f;
            lsum0 += p0 + p1;
            lsum1 += p2 + p3;
            uint32_t h01 = pack_bf16x2(p0, p1);
            uint32_t h23 = pack_bf16x2(p2, p3);
            ph01[nb] = h01; ph23[nb] = h23;
            pl01[nb] = pack_bf16x2(p0 - bflo(h01), p1 - bfhi(h01));
            pl23[nb] = pack_bf16x2(p2 - bflo(h23), p3 - bfhi(h23));
        }

        // ---- O += P V : bf16x3 (PhVh + PhVl + PlVh); P frags from registers
        #pragma unroll
        for (int ks = 0; ks < 4; ks++) {
            uint32_t vfh[4][4], vfl[4][4];
            #pragma unroll
            for (int np = 0; np < 4; np++) {
                uint32_t off = boff0 + (uint32_t)(np * 16 * PITCHB + ks * 32);
                ldmx4(smb + SM_VH + off, vfh[np]);
                ldmx4(smb + SM_VL + off, vfl[np]);
            }
            uint32_t a0 = ph01[2*ks], a1 = ph23[2*ks];
            uint32_t a2 = ph01[2*ks+1], a3 = ph23[2*ks+1];
            uint32_t la0 = pl01[2*ks], la1 = pl23[2*ks];
            uint32_t la2 = pl01[2*ks+1], la3 = pl23[2*ks+1];
            #pragma unroll
            for (int np = 0; np < 4; np++)
                #pragma unroll
                for (int h = 0; h < 2; h++) {
                    int nb = 2 * np + h;
                    mma_bf16(o[nb], a0, a1, a2, a3, vfh[np][2*h], vfh[np][2*h+1]);
                    mma_bf16(o[nb], a0, a1, a2, a3, vfl[np][2*h], vfl[np][2*h+1]);
                    mma_bf16(o[nb], la0, la1, la2, la3, vfh[np][2*h], vfh[np][2*h+1]);
                }
        }
    }

    // ---- epilogue: reduce l across the quad (same row), normalize, store
    lsum0 += __shfl_xor_sync(0xffffffffu, lsum0, 1);
    lsum0 += __shfl_xor_sync(0xffffffffu, lsum0, 2);
    lsum1 += __shfl_xor_sync(0xffffffffu, lsum1, 1);
    lsum1 += __shfl_xor_sync(0xffffffffu, lsum1, 2);
    float inv0 = 1.0f / lsum0;
    float inv1 = 1.0f / lsum1;

    int row0 = q0 + warp * 16 + (lane >> 2);
    float* op0 = Out + ((size_t)bh * SLEN + row0) * DH + 2 * (lane & 3);
    float* op1 = op0 + 8 * DH;
    #pragma unroll
    for (int nb = 0; nb < 8; nb++) {
        *(float2*)(op0 + 8 * nb) = make_float2(o[nb][0] * inv0, o[nb][1] * inv0);
        *(float2*)(op1 + 8 * nb) = make_float2(o[nb][2] * inv1, o[nb][3] * inv1);
    }
}

// ---------------------------------------------------------------------------
extern "C" void kernel_launch(void* const* d_in, const int* in_sizes, int n_in,
                              void* d_out, int out_size) {
    const float* Q = (const float*)d_in[0];
    const float* K = (const float*)d_in[1];
    const float* V = (const float*)d_in[2];
    float* Out = (float*)d_out;

    cudaFuncSetAttribute(attn_mma_kernel,
                         cudaFuncAttributeMaxDynamicSharedMemorySize, SM_TOTAL);
    dim3 grid(SLEN / BQ, BHN);
    attn_mma_kernel<<<grid, NT, SM_TOTAL>>>(Q, K, V, Out);
}

// round 7
// speedup vs baseline: 1.9020x; 1.3140x over previous
#include <cuda_runtime.h>
#include <cstdint>

// Problem constants
#define BHN   64
#define SLEN  1024
#define DH    64
#define BQ    128           // q rows per CTA (16 per warp, 8 warps)
#define NT    256
#define NKT   16
#define PITCHB 144          // smem row pitch bytes (72 bf16) -> conflict-free ldmatrix

#define EXP_SHIFT 40.0f

// smem byte offsets
#define SM_QH 0              // 128 x 144 = 18432
#define SM_QL 18432
#define SM_KH 36864          // 64 x 144 = 9216
#define SM_KL 46080
#define SM_VH 55296          // V row-major (k rows, d cols), like K
#define SM_VL 64512
#define SM_TOTAL 73728

// ---------------------------------------------------------------------------
// helpers
// ---------------------------------------------------------------------------
__device__ __forceinline__ uint32_t smem_u32(const void* p) {
    uint32_t a;
    asm("{ .reg .u64 t; cvta.to.shared.u64 t, %1; cvt.u32.u64 %0, t; }"
        : "=r"(a) : "l"(p));
    return a;
}
__device__ __forceinline__ uint32_t pack_bf16x2(float lo, float hi) {
    uint32_t r;
    asm("cvt.rn.bf16x2.f32 %0, %1, %2;" : "=r"(r) : "f"(hi), "f"(lo));
    return r;
}
__device__ __forceinline__ float bflo(uint32_t p) { return __uint_as_float(p << 16); }
__device__ __forceinline__ float bfhi(uint32_t p) { return __uint_as_float(p & 0xFFFF0000u); }

__device__ __forceinline__ void cvt_split4(float4 v, uint32_t& h0, uint32_t& h1,
                                           uint32_t& l0, uint32_t& l1) {
    h0 = pack_bf16x2(v.x, v.y);
    h1 = pack_bf16x2(v.z, v.w);
    l0 = pack_bf16x2(v.x - bflo(h0), v.y - bfhi(h0));
    l1 = pack_bf16x2(v.z - bflo(h1), v.w - bfhi(h1));
}

__device__ __forceinline__ void ldmx4(uint32_t addr, uint32_t r[4]) {
    asm volatile("ldmatrix.sync.aligned.m8n8.x4.shared.b16 {%0,%1,%2,%3}, [%4];"
                 : "=r"(r[0]), "=r"(r[1]), "=r"(r[2]), "=r"(r[3]) : "r"(addr));
}
__device__ __forceinline__ void ldmx4t(uint32_t addr, uint32_t r[4]) {
    asm volatile("ldmatrix.sync.aligned.m8n8.x4.trans.shared.b16 {%0,%1,%2,%3}, [%4];"
                 : "=r"(r[0]), "=r"(r[1]), "=r"(r[2]), "=r"(r[3]) : "r"(addr));
}

__device__ __forceinline__ void mma_bf16(float c[4], uint32_t a0, uint32_t a1,
                                         uint32_t a2, uint32_t a3,
                                         uint32_t b0, uint32_t b1) {
    asm volatile(
        "mma.sync.aligned.m16n8k16.row.col.f32.bf16.bf16.f32 "
        "{%0,%1,%2,%3}, {%4,%5,%6,%7}, {%8,%9}, {%0,%1,%2,%3};"
        : "+f"(c[0]), "+f"(c[1]), "+f"(c[2]), "+f"(c[3])
        : "r"(a0), "r"(a1), "r"(a2), "r"(a3), "r"(b0), "r"(b1));
}

// ---------------------------------------------------------------------------
// Threefry2x32(key=(0,42), x=(0,i)) x2 interleaved; keep <=> bit31(o0^o1)==0
// ---------------------------------------------------------------------------
__device__ __forceinline__ unsigned rotl32(unsigned x, int r) {
    return __funnelshift_l(x, x, r);
}
__device__ __forceinline__ unsigned tf_keep2(unsigned ia, unsigned ib) {
    const unsigned ks1 = 42u;
    const unsigned ks2 = 42u ^ 0x1BD11BDAu;
    unsigned a0 = 0u, a1 = ia + ks1;
    unsigned b0 = 0u, b1 = ib + ks1;
#define R2(r) { a0 += a1; b0 += b1; a1 = rotl32(a1,(r)); b1 = rotl32(b1,(r)); \
                a1 ^= a0; b1 ^= b0; }
    R2(13) R2(15) R2(26) R2(6)
    a0 += ks1; a1 += ks2 + 1u;  b0 += ks1; b1 += ks2 + 1u;
    R2(17) R2(29) R2(16) R2(24)
    a0 += ks2; a1 += 2u;        b0 += ks2; b1 += 2u;
    R2(13) R2(15) R2(26) R2(6)
    a1 += ks1 + 3u;             b1 += ks1 + 3u;
    R2(17) R2(29) R2(16) R2(24)
    a0 += ks1; a1 += ks2 + 4u;  b0 += ks1; b1 += ks2 + 4u;
    R2(13) R2(15) R2(26) R2(6)
    a0 += ks2; a1 += 5u;        b0 += ks2; b1 += 5u;
#undef R2
    unsigned ka = ((a0 ^ a1) >> 31) ^ 1u;
    unsigned kb = ((b0 ^ b1) >> 31) ^ 1u;
    return ka | (kb << 1);
}

// ---------------------------------------------------------------------------
// bf16x3 HMMA flash attention, inline threefry dropout, fixed-shift softmax.
// V fragments via ldmatrix.trans (V stored row-major like K).
// ---------------------------------------------------------------------------
__global__ void __launch_bounds__(NT, 2) attn_mma_kernel(
    const float* __restrict__ Q,
    const float* __restrict__ K,
    const float* __restrict__ V,
    float* __restrict__ Out)
{
    extern __shared__ char sm[];
    const uint32_t smb = smem_u32(sm);
    const int tid  = threadIdx.x;
    const int lane = tid & 31;
    const int warp = tid >> 5;
    const int bh   = blockIdx.y;
    const int q0   = blockIdx.x * BQ;

    const float* Qb = Q + ((size_t)bh * SLEN + q0) * DH;
    const float* Kb = K + (size_t)bh * SLEN * DH;
    const float* Vb = V + (size_t)bh * SLEN * DH;

    // ---- Q tile -> smem bf16 hi/lo (rows=q, cols=d)
    #pragma unroll
    for (int i = 0; i < 8; i++) {
        int idx = tid + i * NT;              // 0..2047 float4s
        int row = idx >> 4, c4 = idx & 15;
        float4 v = *(const float4*)(Qb + row * DH + c4 * 4);
        uint32_t h0, h1, l0, l1;
        cvt_split4(v, h0, h1, l0, l1);
        *(uint2*)(sm + SM_QH + row * PITCHB + c4 * 8) = make_uint2(h0, h1);
        *(uint2*)(sm + SM_QL + row * PITCHB + c4 * 8) = make_uint2(l0, l1);
    }
    __syncthreads();

    // ldmatrix lane mappings
    // A (m16k16): m0 rows0-7/k0-7, m1 rows8-15/k0-7, m2 rows0-7/k8-15, m3 rows8-15/k8-15
    const int arow = (lane & 7) + ((lane >> 3) & 1) * 8;
    const int ach  = (lane >> 4);
    // B non-trans (K): m0 n0-7/c0, m1 n0-7/c8, m2 n8-15/c0, m3 n8-15/c8
    const uint32_t boff0 =
        (uint32_t)(((lane & 7) + (lane >> 4) * 8) * PITCHB + ((lane >> 3) & 1) * 16);
    // B trans (V row-major): m0 k0-7/n0-7, m1 k8-15/n0-7, m2 k0-7/n8-15, m3 k8-15/n8-15
    const uint32_t toff0 =
        (uint32_t)(((lane & 7) + 8 * ((lane >> 3) & 1)) * PITCHB + 16 * (lane >> 4));
    const uint32_t aoff0 =
        (uint32_t)((warp * 16 + arow) * PITCHB + ach * 16);

    float o[8][4];
    #pragma unroll
    for (int nb = 0; nb < 8; nb++)
        o[nb][0] = o[nb][1] = o[nb][2] = o[nb][3] = 0.0f;
    float lsum0 = 0.0f, lsum1 = 0.0f;

    // threefry element base: row (q0+warp*16+lane/4), col offset 2*(lane&3)
    const unsigned er0 =
        (((unsigned)(bh * SLEN + q0 + warp * 16 + (lane >> 2))) << 10) + 2u * (lane & 3);

    for (int kt = 0; kt < NKT; kt++) {
        __syncthreads();   // prior tile's ldmatrix reads done

        // ---- K and V tiles (both rows=key, cols=d) -> bf16 hi/lo
        const float* Kt = Kb + (size_t)kt * 64 * DH;
        const float* Vt = Vb + (size_t)kt * 64 * DH;
        #pragma unroll
        for (int i = 0; i < 4; i++) {
            int idx = tid + i * NT;          // 0..1023 float4s
            int row = idx >> 4, c4 = idx & 15;
            {
                float4 v = *(const float4*)(Kt + row * DH + c4 * 4);
                uint32_t h0, h1, l0, l1;
                cvt_split4(v, h0, h1, l0, l1);
                *(uint2*)(sm + SM_KH + row * PITCHB + c4 * 8) = make_uint2(h0, h1);
                *(uint2*)(sm + SM_KL + row * PITCHB + c4 * 8) = make_uint2(l0, l1);
            }
            {
                float4 v = *(const float4*)(Vt + row * DH + c4 * 4);
                uint32_t h0, h1, l0, l1;
                cvt_split4(v, h0, h1, l0, l1);
                *(uint2*)(sm + SM_VH + row * PITCHB + c4 * 8) = make_uint2(h0, h1);
                *(uint2*)(sm + SM_VL + row * PITCHB + c4 * 8) = make_uint2(l0, l1);
            }
        }

        // ---- threefry: 32 keep bits (2 rows x 16 cols) — overlaps the loads
        unsigned mask = 0;
        {
            unsigned e0 = er0 + (unsigned)(kt * 64);
            #pragma unroll
            for (int nb = 0; nb < 8; nb++) {
                unsigned ka = tf_keep2(e0 + 8u * nb, e0 + 8u * nb + 1u);
                unsigned kb2 = tf_keep2(e0 + 8192u + 8u * nb, e0 + 8192u + 8u * nb + 1u);
                mask |= (ka | (kb2 << 2)) << (nb * 4);
            }
        }
        __syncthreads();

        // ---- S = Q K^T : bf16x3 (QhKh + QhKl + QlKh)
        float s[8][4];
        #pragma unroll
        for (int nb = 0; nb < 8; nb++)
            s[nb][0] = s[nb][1] = s[nb][2] = s[nb][3] = 0.0f;

        #pragma unroll
        for (int ks = 0; ks < 4; ks++) {
            uint32_t qh[4], ql[4];
            ldmx4(smb + SM_QH + aoff0 + ks * 32, qh);
            ldmx4(smb + SM_QL + aoff0 + ks * 32, ql);
            #pragma unroll
            for (int np = 0; np < 4; np++) {
                uint32_t kfh[4], kfl[4];
                uint32_t off = boff0 + (uint32_t)(np * 16 * PITCHB + ks * 32);
                ldmx4(smb + SM_KH + off, kfh);
                ldmx4(smb + SM_KL + off, kfl);
                #pragma unroll
                for (int h = 0; h < 2; h++) {
                    int nb = 2 * np + h;
                    mma_bf16(s[nb], qh[0], qh[1], qh[2], qh[3], kfh[2*h], kfh[2*h+1]);
                    mma_bf16(s[nb], qh[0], qh[1], qh[2], qh[3], kfl[2*h], kfl[2*h+1]);
                    mma_bf16(s[nb], ql[0], ql[1], ql[2], ql[3], kfh[2*h], kfh[2*h+1]);
                }
            }
        }

        // ---- dropout + fixed-shift softmax + pack P to bf16 hi/lo A-fragments
        uint32_t ph01[8], ph23[8], pl01[8], pl23[8];
        #pragma unroll
        for (int nb = 0; nb < 8; nb++) {
            unsigned mb = mask >> (nb * 4);
            float p0 = (mb & 1u) ? __expf(fmaf(s[nb][0], 2.0f, -EXP_SHIFT)) : 0.0f;
            float p1 = (mb & 2u) ? __expf(fmaf(s[nb][1], 2.0f, -EXP_SHIFT)) : 0.0f;
            float p2 = (mb & 4u) ? __expf(fmaf(s[nb][2], 2.0f, -EXP_SHIFT)) : 0.0f;
            float p3 = (mb & 8u) ? __expf(fmaf(s[nb][3], 2.0f, -EXP_SHIFT)) : 0.0f;
            lsum0 += p0 + p1;
            lsum1 += p2 + p3;
            uint32_t h01 = pack_bf16x2(p0, p1);
            uint32_t h23 = pack_bf16x2(p2, p3);
            ph01[nb] = h01; ph23[nb] = h23;
            pl01[nb] = pack_bf16x2(p0 - bflo(h01), p1 - bfhi(h01));
            pl23[nb] = pack_bf16x2(p2 - bflo(h23), p3 - bfhi(h23));
        }

        // ---- O += P V : bf16x3 (PhVh + PhVl + PlVh); V frags via ldmatrix.trans
        #pragma unroll
        for (int ks = 0; ks < 4; ks++) {
            uint32_t a0 = ph01[2*ks],   a1 = ph23[2*ks];
            uint32_t a2 = ph01[2*ks+1], a3 = ph23[2*ks+1];
            uint32_t la0 = pl01[2*ks],   la1 = pl23[2*ks];
            uint32_t la2 = pl01[2*ks+1], la3 = pl23[2*ks+1];
            #pragma unroll
            for (int np = 0; np < 4; np++) {
                uint32_t vfh[4], vfl[4];
                uint32_t off = toff0 + (uint32_t)(ks * 16 * PITCHB + np * 32);
                ldmx4t(smb + SM_VH + off, vfh);
                ldmx4t(smb + SM_VL + off, vfl);
                #pragma unroll
                for (int h = 0; h < 2; h++) {
                    int nb = 2 * np + h;
                    mma_bf16(o[nb], a0, a1, a2, a3, vfh[2*h], vfh[2*h+1]);
                    mma_bf16(o[nb], a0, a1, a2, a3, vfl[2*h], vfl[2*h+1]);
                    mma_bf16(o[nb], la0, la1, la2, la3, vfh[2*h], vfh[2*h+1]);
                }
            }
        }
    }

    // ---- epilogue: reduce l across the quad (same row), normalize, store
    lsum0 += __shfl_xor_sync(0xffffffffu, lsum0, 1);
    lsum0 += __shfl_xor_sync(0xffffffffu, lsum0, 2);
    lsum1 += __shfl_xor_sync(0xffffffffu, lsum1, 1);
    lsum1 += __shfl_xor_sync(0xffffffffu, lsum1, 2);
    float inv0 = 1.0f / lsum0;
    float inv1 = 1.0f / lsum1;

    int row0 = q0 + warp * 16 + (lane >> 2);
    float* op0 = Out + ((size_t)bh * SLEN + row0) * DH + 2 * (lane & 3);
    float* op1 = op0 + 8 * DH;
    #pragma unroll
    for (int nb = 0; nb < 8; nb++) {
        *(float2*)(op0 + 8 * nb) = make_float2(o[nb][0] * inv0, o[nb][1] * inv0);
        *(float2*)(op1 + 8 * nb) = make_float2(o[nb][2] * inv1, o[nb][3] * inv1);
    }
}

// ---------------------------------------------------------------------------
extern "C" void kernel_launch(void* const* d_in, const int* in_sizes, int n_in,
                              void* d_out, int out_size) {
    const float* Q = (const float*)d_in[0];
    const float* K = (const float*)d_in[1];
    const float* V = (const float*)d_in[2];
    float* Out = (float*)d_out;

    cudaFuncSetAttribute(attn_mma_kernel,
                         cudaFuncAttributeMaxDynamicSharedMemorySize, SM_TOTAL);
    dim3 grid(SLEN / BQ, BHN);
    attn_mma_kernel<<<grid, NT, SM_TOTAL>>>(Q, K, V, Out);
}

// round 8
// speedup vs baseline: 1.9624x; 1.0317x over previous
#include <cuda_runtime.h>
#include <cstdint>

// Problem constants
#define BHN   64
#define SLEN  1024
#define DH    64
#define BQ    128           // q rows per CTA (16 per warp, 8 warps)
#define NT    256
#define NKT   16
#define PITCHB 144          // smem row pitch bytes (72 bf16) -> conflict-free ldmatrix

#define EXP_SHIFT 40.0f

// smem byte offsets
#define SM_QH 0              // 128 x 144 = 18432
#define SM_QL 18432
#define SM_KH 36864          // 64 x 144 = 9216
#define SM_KL 46080
#define SM_VH 55296          // V row-major (k rows, d cols), like K
#define SM_VL 64512
#define SM_TOTAL 73728

// ---------------------------------------------------------------------------
// helpers
// ---------------------------------------------------------------------------
__device__ __forceinline__ uint32_t smem_u32(const void* p) {
    uint32_t a;
    asm("{ .reg .u64 t; cvta.to.shared.u64 t, %1; cvt.u32.u64 %0, t; }"
        : "=r"(a) : "l"(p));
    return a;
}
__device__ __forceinline__ uint32_t pack_bf16x2(float lo, float hi) {
    uint32_t r;
    asm("cvt.rn.bf16x2.f32 %0, %1, %2;" : "=r"(r) : "f"(hi), "f"(lo));
    return r;
}
__device__ __forceinline__ float bflo(uint32_t p) { return __uint_as_float(p << 16); }
__device__ __forceinline__ float bfhi(uint32_t p) { return __uint_as_float(p & 0xFFFF0000u); }

__device__ __forceinline__ void cvt_split4(float4 v, uint32_t& h0, uint32_t& h1,
                                           uint32_t& l0, uint32_t& l1) {
    h0 = pack_bf16x2(v.x, v.y);
    h1 = pack_bf16x2(v.z, v.w);
    l0 = pack_bf16x2(v.x - bflo(h0), v.y - bfhi(h0));
    l1 = pack_bf16x2(v.z - bflo(h1), v.w - bfhi(h1));
}

__device__ __forceinline__ void ldmx4(uint32_t addr, uint32_t r[4]) {
    asm volatile("ldmatrix.sync.aligned.m8n8.x4.shared.b16 {%0,%1,%2,%3}, [%4];"
                 : "=r"(r[0]), "=r"(r[1]), "=r"(r[2]), "=r"(r[3]) : "r"(addr));
}
__device__ __forceinline__ void ldmx4t(uint32_t addr, uint32_t r[4]) {
    asm volatile("ldmatrix.sync.aligned.m8n8.x4.trans.shared.b16 {%0,%1,%2,%3}, [%4];"
                 : "=r"(r[0]), "=r"(r[1]), "=r"(r[2]), "=r"(r[3]) : "r"(addr));
}

__device__ __forceinline__ void mma_bf16(float c[4], uint32_t a0, uint32_t a1,
                                         uint32_t a2, uint32_t a3,
                                         uint32_t b0, uint32_t b1) {
    asm volatile(
        "mma.sync.aligned.m16n8k16.row.col.f32.bf16.bf16.f32 "
        "{%0,%1,%2,%3}, {%4,%5,%6,%7}, {%8,%9}, {%0,%1,%2,%3};"
        : "+f"(c[0]), "+f"(c[1]), "+f"(c[2]), "+f"(c[3])
        : "r"(a0), "r"(a1), "r"(a2), "r"(a3), "r"(b0), "r"(b1));
}

// ---------------------------------------------------------------------------
// Threefry2x32(key=(0,42), x=(0,i)) x4 interleaved, pipe-balanced:
// streams a,b use IADD3 (alu pipe); streams c,d use IMAD via opaque 'one'
// (fma pipe). keep <=> bit31(o0^o1)==0.
// Returns bit0=keep(ia), bit1=keep(ib), bit2=keep(ic), bit3=keep(id).
// ---------------------------------------------------------------------------
__device__ __forceinline__ unsigned rotl32(unsigned x, int r) {
    return __funnelshift_l(x, x, r);
}
__device__ __forceinline__ unsigned uimad(unsigned a, unsigned one, unsigned c) {
    unsigned r;
    asm("mad.lo.u32 %0, %1, %2, %3;" : "=r"(r) : "r"(a), "r"(one), "r"(c));
    return r;
}
__device__ __forceinline__ unsigned tf_keep4(unsigned ia, unsigned ib,
                                             unsigned ic, unsigned id,
                                             unsigned one) {
    const unsigned ks1 = 42u;
    const unsigned ks2 = 42u ^ 0x1BD11BDAu;
    unsigned a0 = 0u, a1 = ia + ks1;
    unsigned b0 = 0u, b1 = ib + ks1;
    unsigned c0 = 0u, c1 = uimad(ic, one, ks1);
    unsigned d0 = 0u, d1 = uimad(id, one, ks1);
#define R4(r) { a0 += a1; b0 += b1;                                          \
                c0 = uimad(c1, one, c0); d0 = uimad(d1, one, d0);            \
                a1 = rotl32(a1,(r)) ^ a0; b1 = rotl32(b1,(r)) ^ b0;          \
                c1 = rotl32(c1,(r)) ^ c0; d1 = rotl32(d1,(r)) ^ d0; }
#define INJ4(kx, ky) { a0 += (kx); b0 += (kx);                               \
                c0 = uimad((kx), one, c0); d0 = uimad((kx), one, d0);        \
                a1 += (ky); b1 += (ky);                                      \
                c1 = uimad((ky), one, c1); d1 = uimad((ky), one, d1); }
    R4(13) R4(15) R4(26) R4(6)
    INJ4(ks1, ks2 + 1u)
    R4(17) R4(29) R4(16) R4(24)
    INJ4(ks2, 2u)
    R4(13) R4(15) R4(26) R4(6)
    INJ4(0u, ks1 + 3u)
    R4(17) R4(29) R4(16) R4(24)
    INJ4(ks1, ks2 + 4u)
    R4(13) R4(15) R4(26) R4(6)
    INJ4(ks2, 5u)
#undef R4
#undef INJ4
    unsigned ka = ((a0 ^ a1) >> 31) ^ 1u;
    unsigned kb = ((b0 ^ b1) >> 31) ^ 1u;
    unsigned kc = ((c0 ^ c1) >> 31) ^ 1u;
    unsigned kd = ((d0 ^ d1) >> 31) ^ 1u;
    return ka | (kb << 1) | (kc << 2) | (kd << 3);
}

// ---------------------------------------------------------------------------
// bf16x3 HMMA flash attention, inline threefry dropout, fixed-shift softmax.
// V fragments via ldmatrix.trans (V stored row-major like K).
// ---------------------------------------------------------------------------
__global__ void __launch_bounds__(NT, 2) attn_mma_kernel(
    const float* __restrict__ Q,
    const float* __restrict__ K,
    const float* __restrict__ V,
    float* __restrict__ Out)
{
    extern __shared__ char sm[];
    const uint32_t smb = smem_u32(sm);
    const int tid  = threadIdx.x;
    const int lane = tid & 31;
    const int warp = tid >> 5;
    const int bh   = blockIdx.y;
    const int q0   = blockIdx.x * BQ;
    // opaque 1 (ptxas cannot fold %ntid) -> keeps IMADs on the fma pipe
    const unsigned one = min((unsigned)blockDim.x, 1u);

    const float* Qb = Q + ((size_t)bh * SLEN + q0) * DH;
    const float* Kb = K + (size_t)bh * SLEN * DH;
    const float* Vb = V + (size_t)bh * SLEN * DH;

    // ---- Q tile -> smem bf16 hi/lo (rows=q, cols=d)
    #pragma unroll
    for (int i = 0; i < 8; i++) {
        int idx = tid + i * NT;              // 0..2047 float4s
        int row = idx >> 4, c4 = idx & 15;
        float4 v = *(const float4*)(Qb + row * DH + c4 * 4);
        uint32_t h0, h1, l0, l1;
        cvt_split4(v, h0, h1, l0, l1);
        *(uint2*)(sm + SM_QH + row * PITCHB + c4 * 8) = make_uint2(h0, h1);
        *(uint2*)(sm + SM_QL + row * PITCHB + c4 * 8) = make_uint2(l0, l1);
    }
    __syncthreads();

    // ldmatrix lane mappings
    const int arow = (lane & 7) + ((lane >> 3) & 1) * 8;
    const int ach  = (lane >> 4);
    const uint32_t boff0 =
        (uint32_t)(((lane & 7) + (lane >> 4) * 8) * PITCHB + ((lane >> 3) & 1) * 16);
    const uint32_t toff0 =
        (uint32_t)(((lane & 7) + 8 * ((lane >> 3) & 1)) * PITCHB + 16 * (lane >> 4));
    const uint32_t aoff0 =
        (uint32_t)((warp * 16 + arow) * PITCHB + ach * 16);

    float o[8][4];
    #pragma unroll
    for (int nb = 0; nb < 8; nb++)
        o[nb][0] = o[nb][1] = o[nb][2] = o[nb][3] = 0.0f;
    float lsum0 = 0.0f, lsum1 = 0.0f;

    // threefry element base: row (q0+warp*16+lane/4), col offset 2*(lane&3)
    const unsigned er0 =
        (((unsigned)(bh * SLEN + q0 + warp * 16 + (lane >> 2))) << 10) + 2u * (lane & 3);

    for (int kt = 0; kt < NKT; kt++) {
        __syncthreads();   // prior tile's ldmatrix reads done

        // ---- K and V tiles -> bf16 hi/lo, threefry interleaved (fills LDG latency)
        const float* Kt = Kb + (size_t)kt * 64 * DH;
        const float* Vt = Vb + (size_t)kt * 64 * DH;
        unsigned mask = 0;
        const unsigned e0 = er0 + (unsigned)(kt * 64);
        #pragma unroll
        for (int i = 0; i < 4; i++) {
            int idx = tid + i * NT;          // 0..1023 float4s
            int row = idx >> 4, c4 = idx & 15;
            {
                float4 v = *(const float4*)(Kt + row * DH + c4 * 4);
                uint32_t h0, h1, l0, l1;
                cvt_split4(v, h0, h1, l0, l1);
                *(uint2*)(sm + SM_KH + row * PITCHB + c4 * 8) = make_uint2(h0, h1);
                *(uint2*)(sm + SM_KL + row * PITCHB + c4 * 8) = make_uint2(l0, l1);
            }
            {
                float4 v = *(const float4*)(Vt + row * DH + c4 * 4);
                uint32_t h0, h1, l0, l1;
                cvt_split4(v, h0, h1, l0, l1);
                *(uint2*)(sm + SM_VH + row * PITCHB + c4 * 8) = make_uint2(h0, h1);
                *(uint2*)(sm + SM_VL + row * PITCHB + c4 * 8) = make_uint2(l0, l1);
            }
            // 8 keep bits: rows (r0, r0+8) x cols (16i, 16i+1, 16i+8, 16i+9)
            unsigned e = e0 + 16u * i;
            mask |= tf_keep4(e,      e + 1u,      e + 8192u, e + 8193u, one) << (8 * i);
            mask |= tf_keep4(e + 8u, e + 9u,      e + 8200u, e + 8201u, one) << (8 * i + 4);
        }
        __syncthreads();

        // ---- S = Q K^T : bf16x3 (QhKh + QhKl + QlKh)
        float s[8][4];
        #pragma unroll
        for (int nb = 0; nb < 8; nb++)
            s[nb][0] = s[nb][1] = s[nb][2] = s[nb][3] = 0.0f;

        #pragma unroll
        for (int ks = 0; ks < 4; ks++) {
            uint32_t qh[4], ql[4];
            ldmx4(smb + SM_QH + aoff0 + ks * 32, qh);
            ldmx4(smb + SM_QL + aoff0 + ks * 32, ql);
            #pragma unroll
            for (int np = 0; np < 4; np++) {
                uint32_t kfh[4], kfl[4];
                uint32_t off = boff0 + (uint32_t)(np * 16 * PITCHB + ks * 32);
                ldmx4(smb + SM_KH + off, kfh);
                ldmx4(smb + SM_KL + off, kfl);
                #pragma unroll
                for (int h = 0; h < 2; h++) {
                    int nb = 2 * np + h;
                    mma_bf16(s[nb], qh[0], qh[1], qh[2], qh[3], kfh[2*h], kfh[2*h+1]);
                    mma_bf16(s[nb], qh[0], qh[1], qh[2], qh[3], kfl[2*h], kfl[2*h+1]);
                    mma_bf16(s[nb], ql[0], ql[1], ql[2], ql[3], kfh[2*h], kfh[2*h+1]);
                }
            }
        }

        // ---- dropout + fixed-shift softmax + pack P to bf16 hi/lo A-fragments
        uint32_t ph01[8], ph23[8], pl01[8], pl23[8];
        #pragma unroll
        for (int nb = 0; nb < 8; nb++) {
            unsigned mb = mask >> (nb * 4);
            float p0 = (mb & 1u) ? __expf(fmaf(s[nb][0], 2.0f, -EXP_SHIFT)) : 0.0f;
            float p1 = (mb & 2u) ? __expf(fmaf(s[nb][1], 2.0f, -EXP_SHIFT)) : 0.0f;
            float p2 = (mb & 4u) ? __expf(fmaf(s[nb][2], 2.0f, -EXP_SHIFT)) : 0.0f;
            float p3 = (mb & 8u) ? __expf(fmaf(s[nb][3], 2.0f, -EXP_SHIFT)) : 0.0f;
            lsum0 += p0 + p1;
            lsum1 += p2 + p3;
            uint32_t h01 = pack_bf16x2(p0, p1);
            uint32_t h23 = pack_bf16x2(p2, p3);
            ph01[nb] = h01; ph23[nb] = h23;
            pl01[nb] = pack_bf16x2(p0 - bflo(h01), p1 - bfhi(h01));
            pl23[nb] = pack_bf16x2(p2 - bflo(h23), p3 - bfhi(h23));
        }

        // ---- O += P V : bf16x3 (PhVh + PhVl + PlVh); V frags via ldmatrix.trans
        #pragma unroll
        for (int ks = 0; ks < 4; ks++) {
            uint32_t a0 = ph01[2*ks],   a1 = ph23[2*ks];
            uint32_t a2 = ph01[2*ks+1], a3 = ph23[2*ks+1];
            uint32_t la0 = pl01[2*ks],   la1 = pl23[2*ks];
            uint32_t la2 = pl01[2*ks+1], la3 = pl23[2*ks+1];
            #pragma unroll
            for (int np = 0; np < 4; np++) {
                uint32_t vfh[4], vfl[4];
                uint32_t off = toff0 + (uint32_t)(ks * 16 * PITCHB + np * 32);
                ldmx4t(smb + SM_VH + off, vfh);
                ldmx4t(smb + SM_VL + off, vfl);
                #pragma unroll
                for (int h = 0; h < 2; h++) {
                    int nb = 2 * np + h;
                    mma_bf16(o[nb], a0, a1, a2, a3, vfh[2*h], vfh[2*h+1]);
                    mma_bf16(o[nb], a0, a1, a2, a3, vfl[2*h], vfl[2*h+1]);
                    mma_bf16(o[nb], la0, la1, la2, la3, vfh[2*h], vfh[2*h+1]);
                }
            }
        }
    }

    // ---- epilogue: reduce l across the quad (same row), normalize, store
    lsum0 += __shfl_xor_sync(0xffffffffu, lsum0, 1);
    lsum0 += __shfl_xor_sync(0xffffffffu, lsum0, 2);
    lsum1 += __shfl_xor_sync(0xffffffffu, lsum1, 1);
    lsum1 += __shfl_xor_sync(0xffffffffu, lsum1, 2);
    float inv0 = 1.0f / lsum0;
    float inv1 = 1.0f / lsum1;

    int row0 = q0 + warp * 16 + (lane >> 2);
    float* op0 = Out + ((size_t)bh * SLEN + row0) * DH + 2 * (lane & 3);
    float* op1 = op0 + 8 * DH;
    #pragma unroll
    for (int nb = 0; nb < 8; nb++) {
        *(float2*)(op0 + 8 * nb) = make_float2(o[nb][0] * inv0, o[nb][1] * inv0);
        *(float2*)(op1 + 8 * nb) = make_float2(o[nb][2] * inv1, o[nb][3] * inv1);
    }
}

// ---------------------------------------------------------------------------
extern "C" void kernel_launch(void* const* d_in, const int* in_sizes, int n_in,
                              void* d_out, int out_size) {
    const float* Q = (const float*)d_in[0];
    const float* K = (const float*)d_in[1];
    const float* V = (const float*)d_in[2];
    float* Out = (float*)d_out;

    cudaFuncSetAttribute(attn_mma_kernel,
                         cudaFuncAttributeMaxDynamicSharedMemorySize, SM_TOTAL);
    dim3 grid(SLEN / BQ, BHN);
    attn_mma_kernel<<<grid, NT, SM_TOTAL>>>(Q, K, V, Out);
}